// round 13
// baseline (speedup 1.0000x reference)
#include <cuda_runtime.h>
#include <cuda_fp16.h>
#include <cstdint>
#include <math.h>

// ---------------------------------------------------------------------------
// Problem constants
// ---------------------------------------------------------------------------
#define BB     8
#define NHID   256
#define LL     2048
#define DD     512            // q/k/v channels
#define DOUT   2048
#define MM     (BB*LL)        // 16384
#define NQKV   1536           // q|k|v fused N
#define K1     256            // QKV GEMM K
#define K2     512            // WO GEMM K

// B-resident GEMM geometry: tiles 128(M) x 128(N), K chunked by 64.
#define CHUNK  16384           // 128 rows x 64 k x 2B, SWZ 128B rows
#define QKT    4               // K1/64
#define WKT    8               // K2/64
#define Q_AOFF (QKT*CHUNK)     // 65536
#define Q_SMEM (Q_AOFF + 3*CHUNK)   // 114688 (112KB) -> 2 CTAs/SM
#define W_AOFF (WKT*CHUNK)     // 131072
#define W_SMEM (W_AOFF + 3*CHUNK)   // 180224 (176KB) -> 1 CTA/SM

// ---------------------------------------------------------------------------
// Scratch (device globals — sanctioned no-alloc path)
// ---------------------------------------------------------------------------
__device__ __half g_A1[(size_t)MM * K1];     // x^T  [m][k] fp16
__device__ __half g_B1[(size_t)NQKV * K1];   // [Wq|Wk|Wv]^T [n][k] fp16
__device__ __half g_A2[(size_t)MM * K2];     // att  [m][k] fp16
__device__ __half g_B2[(size_t)DOUT * K2];   // Wo^T [n][k] fp16
__device__ __half g_qkv[(size_t)MM * NQKV];  // fp16 q|k|v (bias included)

// ---------------------------------------------------------------------------
// Helpers (base-target PTX: cp.async, ldmatrix, mma.sync)
// ---------------------------------------------------------------------------
__device__ __forceinline__ uint32_t smem_u32(const void* p) {
    uint32_t a;
    asm("{ .reg .u64 t; cvta.to.shared.u64 t, %1; cvt.u32.u64 %0, t; }"
        : "=r"(a) : "l"(p));
    return a;
}

#define SWZ(x) ((x) ^ ((((x) >> 7) & 7) << 4))   // Swizzle<3,4,3>, 128B rows

#define CPASYNC16(dst, src) \
    asm volatile("cp.async.cg.shared.global [%0], [%1], 16;" \
                 :: "r"(dst), "l"(src))
#define CPCOMMIT() asm volatile("cp.async.commit_group;" ::: "memory")
#define CPWAIT(n)  asm volatile("cp.async.wait_group %0;" :: "n"(n) : "memory")

__device__ __forceinline__ void ldsm4(uint32_t& r0, uint32_t& r1,
                                      uint32_t& r2, uint32_t& r3, uint32_t a) {
    asm volatile("ldmatrix.sync.aligned.m8n8.x4.shared.b16 {%0,%1,%2,%3}, [%4];"
                 : "=r"(r0), "=r"(r1), "=r"(r2), "=r"(r3) : "r"(a));
}

__device__ __forceinline__ void mma16816(float* d, const uint32_t* a,
                                         const uint32_t* b) {
    asm volatile(
        "mma.sync.aligned.m16n8k16.row.col.f32.f16.f16.f32 "
        "{%0,%1,%2,%3}, {%4,%5,%6,%7}, {%8,%9}, {%0,%1,%2,%3};"
        : "+f"(d[0]), "+f"(d[1]), "+f"(d[2]), "+f"(d[3])
        : "r"(a[0]), "r"(a[1]), "r"(a[2]), "r"(a[3]), "r"(b[0]), "r"(b[1]));
}

// ---------------------------------------------------------------------------
// QKV GEMM (B-resident): g_qkv[m][n] = fp16( A1[m].B1[n] + bias[n] )
// TH=128: 4 warps as 2(M)x2(N), warp tile 64x64. B panel 64KB resident,
// A streamed in 16KB chunks through a 3-deep cp.async ring. 2 CTAs/SM.
// grid (12, 32): n-tile x m-group-of-4.
// ---------------------------------------------------------------------------
__device__ __forceinline__ float qkv_bias(int n, const float* __restrict__ bq,
                                          const float* __restrict__ bk,
                                          const float* __restrict__ bv) {
    if (n < DD)     return bq[n];
    if (n < 2 * DD) return bk[n - DD];
    return bv[n - 2 * DD];
}

__global__ __launch_bounds__(128, 2)
void qkv_gemm(const float* __restrict__ bq, const float* __restrict__ bk,
              const float* __restrict__ bv) {
    extern __shared__ __align__(1024) char smem[];
    const uint32_t sb = smem_u32(smem);
    const int tid = threadIdx.x, wid = tid >> 5, lane = tid & 31;
    const int n0  = blockIdx.x * 128;
    const int m0g = blockIdx.y * 512;          // 4 m-tiles of 128
    const int wm  = (wid & 1) * 64;
    const int wn  = (wid >> 1) * 64;

    // Prologue: whole B panel (4 chunks) + A chunk0 -> group0; A chunk1 -> group1
    {
        const __half* Bsrc = g_B1 + (size_t)n0 * K1;
#pragma unroll
        for (int i = 0; i < 32; ++i) {
            const int idx = tid + i * 128;          // 0..4095
            const int ch = idx >> 10, r = (idx >> 3) & 127, c = idx & 7;
            CPASYNC16(sb + ch * CHUNK + SWZ(r * 128 + c * 16),
                      Bsrc + (size_t)r * K1 + ch * 64 + c * 8);
        }
    }
    auto load_a = [&](int j, int buf) {            // chunk j = (mt=j>>2, kc=j&3)
        const __half* Asrc = g_A1 + (size_t)(m0g + (j >> 2) * 128) * K1 + (j & 3) * 64;
#pragma unroll
        for (int i = 0; i < 8; ++i) {
            const int idx = tid + i * 128;          // 0..1023
            const int r = idx >> 3, c = idx & 7;
            CPASYNC16(sb + Q_AOFF + buf * CHUNK + SWZ(r * 128 + c * 16),
                      Asrc + (size_t)r * K1 + c * 8);
        }
    };
    load_a(0, 0); CPCOMMIT();
    load_a(1, 1); CPCOMMIT();

    float acc[4][8][4];
#pragma unroll
    for (int i = 0; i < 4; ++i)
#pragma unroll
        for (int j = 0; j < 8; ++j)
#pragma unroll
            for (int r = 0; r < 4; ++r) acc[i][j][r] = 0.f;

    const int aRow = wm + (lane & 15);
    const int aCol = (lane >> 4) << 4;
    const int bRow = wn + ((lane >> 4) << 3) + (lane & 7);
    const int bCol = ((lane >> 3) & 1) << 4;

    for (int i = 0; i < 16; ++i) {
        CPWAIT(1);
        __syncthreads();
        const uint32_t as = sb + Q_AOFF + (i % 3) * CHUNK;
        const uint32_t bs = sb + (i & 3) * CHUNK;
#pragma unroll
        for (int ks = 0; ks < 4; ++ks) {
            uint32_t af[4][4], bf[4][4];
#pragma unroll
            for (int mi = 0; mi < 4; ++mi) {
                const uint32_t a = as + SWZ((aRow + mi * 16) * 128 + ks * 32 + aCol);
                ldsm4(af[mi][0], af[mi][1], af[mi][2], af[mi][3], a);
            }
#pragma unroll
            for (int ni = 0; ni < 4; ++ni) {
                const uint32_t a = bs + SWZ((bRow + ni * 16) * 128 + ks * 32 + bCol);
                ldsm4(bf[ni][0], bf[ni][1], bf[ni][2], bf[ni][3], a);
            }
#pragma unroll
            for (int mi = 0; mi < 4; ++mi)
#pragma unroll
                for (int ni = 0; ni < 4; ++ni) {
                    mma16816(acc[mi][ni * 2],     af[mi], &bf[ni][0]);
                    mma16816(acc[mi][ni * 2 + 1], af[mi], &bf[ni][2]);
                }
        }
        const int nx = i + 2;
        if (nx < 16) load_a(nx, nx % 3);
        CPCOMMIT();

        if ((i & 3) == 3) {
            // m-tile finished: epilogue straight from registers (overlaps ring loads)
            const int mt  = i >> 2;
            const int wmg = m0g + mt * 128 + wm;
            const int wng = n0 + wn;
#pragma unroll
            for (int mi = 0; mi < 4; ++mi) {
                const int r0 = wmg + mi * 16 + (lane >> 2);
#pragma unroll
                for (int ni = 0; ni < 8; ++ni) {
                    const int n = wng + ni * 8 + 2 * (lane & 3);
                    const float b0 = qkv_bias(n, bq, bk, bv);
                    const float b1 = qkv_bias(n + 1, bq, bk, bv);
                    const __half2 v0 = __floats2half2_rn(acc[mi][ni][0] + b0, acc[mi][ni][1] + b1);
                    const __half2 v1 = __floats2half2_rn(acc[mi][ni][2] + b0, acc[mi][ni][3] + b1);
                    *reinterpret_cast<__half2*>(&g_qkv[(size_t)r0 * NQKV + n])       = v0;
                    *reinterpret_cast<__half2*>(&g_qkv[(size_t)(r0 + 8) * NQKV + n]) = v1;
#pragma unroll
                    for (int r = 0; r < 4; ++r) acc[mi][ni][r] = 0.f;
                }
            }
        }
    }
}

// ---------------------------------------------------------------------------
// WO GEMM (B-resident): out[b][n][l] = A2[m].B2[n] + bo[n], m = b*LL + l.
// TH=256: 8 warps as 2(M)x4(N), warp tile 64x32. B panel 128KB resident,
// A streamed in 16KB chunks (3-deep ring). Direct scattered epilogue
// (32B sector runs per n-row, no smem transpose). grid (16, 32).
// ---------------------------------------------------------------------------
__global__ __launch_bounds__(256, 1)
void wo_gemm(const float* __restrict__ bo, float* __restrict__ out) {
    extern __shared__ __align__(1024) char smem[];
    const uint32_t sb = smem_u32(smem);
    const int tid = threadIdx.x, wid = tid >> 5, lane = tid & 31;
    const int n0  = blockIdx.x * 128;
    const int m0g = blockIdx.y * 512;          // 4 m-tiles, 512 rows: same batch
    const int b   = m0g / LL;
    const int l0g = m0g % LL;
    const int wm  = (wid & 1) * 64;
    const int wn  = (wid >> 1) * 32;
    float* outb = out + (size_t)b * DOUT * LL;

    // Prologue: whole B panel (8 chunks) + A chunk0 -> group0; A chunk1 -> group1
    {
        const __half* Bsrc = g_B2 + (size_t)n0 * K2;
#pragma unroll
        for (int i = 0; i < 32; ++i) {
            const int idx = tid + i * 256;          // 0..8191
            const int ch = idx >> 10, r = (idx >> 3) & 127, c = idx & 7;
            CPASYNC16(sb + ch * CHUNK + SWZ(r * 128 + c * 16),
                      Bsrc + (size_t)r * K2 + ch * 64 + c * 8);
        }
    }
    auto load_a = [&](int j, int buf) {            // chunk j = (mt=j>>3, kc=j&7)
        const __half* Asrc = g_A2 + (size_t)(m0g + (j >> 3) * 128) * K2 + (j & 7) * 64;
#pragma unroll
        for (int i = 0; i < 4; ++i) {
            const int idx = tid + i * 256;          // 0..1023
            const int r = idx >> 3, c = idx & 7;
            CPASYNC16(sb + W_AOFF + buf * CHUNK + SWZ(r * 128 + c * 16),
                      Asrc + (size_t)r * K2 + c * 8);
        }
    };
    load_a(0, 0); CPCOMMIT();
    load_a(1, 1); CPCOMMIT();

    float acc[4][4][4];
#pragma unroll
    for (int i = 0; i < 4; ++i)
#pragma unroll
        for (int j = 0; j < 4; ++j)
#pragma unroll
            for (int r = 0; r < 4; ++r) acc[i][j][r] = 0.f;

    const int aRow = wm + (lane & 15);
    const int aCol = (lane >> 4) << 4;
    const int bRow = wn + ((lane >> 4) << 3) + (lane & 7);
    const int bCol = ((lane >> 3) & 1) << 4;

    for (int i = 0; i < 32; ++i) {
        CPWAIT(1);
        __syncthreads();
        const uint32_t as = sb + W_AOFF + (i % 3) * CHUNK;
        const uint32_t bs = sb + (i & 7) * CHUNK;
#pragma unroll
        for (int ks = 0; ks < 4; ++ks) {
            uint32_t af[4][4], bf[2][4];
#pragma unroll
            for (int mi = 0; mi < 4; ++mi) {
                const uint32_t a = as + SWZ((aRow + mi * 16) * 128 + ks * 32 + aCol);
                ldsm4(af[mi][0], af[mi][1], af[mi][2], af[mi][3], a);
            }
#pragma unroll
            for (int ni = 0; ni < 2; ++ni) {
                const uint32_t a = bs + SWZ((bRow + ni * 16) * 128 + ks * 32 + bCol);
                ldsm4(bf[ni][0], bf[ni][1], bf[ni][2], bf[ni][3], a);
            }
#pragma unroll
            for (int mi = 0; mi < 4; ++mi)
#pragma unroll
                for (int ni = 0; ni < 2; ++ni) {
                    mma16816(acc[mi][ni * 2],     af[mi], &bf[ni][0]);
                    mma16816(acc[mi][ni * 2 + 1], af[mi], &bf[ni][2]);
                }
        }
        const int nx = i + 2;
        if (nx < 32) load_a(nx, nx % 3);
        CPCOMMIT();

        if ((i & 7) == 7) {
            // m-tile finished: direct transposed scatter (32B runs per n-row)
            const int mt = i >> 3;
            const int lw = l0g + mt * 128 + wm;
#pragma unroll
            for (int mi = 0; mi < 4; ++mi) {
                const int l = lw + mi * 16 + (lane >> 2);
#pragma unroll
                for (int nj = 0; nj < 4; ++nj) {
                    const int n = n0 + wn + nj * 8 + 2 * (lane & 3);
                    const float b0 = bo[n], b1 = bo[n + 1];
                    outb[(size_t)n * LL + l]           = acc[mi][nj][0] + b0;
                    outb[(size_t)(n + 1) * LL + l]     = acc[mi][nj][1] + b1;
                    outb[(size_t)n * LL + l + 8]       = acc[mi][nj][2] + b0;
                    outb[(size_t)(n + 1) * LL + l + 8] = acc[mi][nj][3] + b1;
#pragma unroll
                    for (int r = 0; r < 4; ++r) acc[mi][nj][r] = 0.f;
                }
            }
        }
    }
}

// ---------------------------------------------------------------------------
// Conversions (fp32 -> fp16, with transposes)
// ---------------------------------------------------------------------------
__global__ __launch_bounds__(1024)
void conv_x_kernel(const float* __restrict__ x) {
    __shared__ float t[32][33];
    const int b  = blockIdx.z;
    const int c0 = blockIdx.y * 32, l0 = blockIdx.x * 32;
    const int tx = threadIdx.x, ty = threadIdx.y;
    t[ty][tx] = x[((size_t)(b * NHID + c0 + ty)) * LL + l0 + tx];
    __syncthreads();
    g_A1[(size_t)(b * LL + l0 + ty) * K1 + c0 + tx] = __float2half(t[tx][ty]);
}

__global__ __launch_bounds__(1024)
void conv_w_all(const float* __restrict__ Wq, const float* __restrict__ Wk,
                const float* __restrict__ Wv, const float* __restrict__ Wo) {
    __shared__ float t[32][33];
    const int bid = blockIdx.x;
    const float* W;
    __half* dst;
    int N, roff, dstride, lb, ntiles;
    if (bid < 384) {
        const int sel = bid >> 7;
        lb = bid & 127;
        W = (sel == 0) ? Wq : (sel == 1) ? Wk : Wv;
        dst = g_B1; N = DD; roff = sel * DD; dstride = K1; ntiles = DD / 32;
    } else {
        lb = bid - 384;
        W = Wo; dst = g_B2; N = DOUT; roff = 0; dstride = K2; ntiles = DOUT / 32;
    }
    const int n0 = (lb % ntiles) * 32;
    const int k0 = (lb / ntiles) * 32;
    const int tx = threadIdx.x, ty = threadIdx.y;
    t[ty][tx] = W[(size_t)(k0 + ty) * N + n0 + tx];
    __syncthreads();
    dst[(size_t)(roff + n0 + ty) * dstride + k0 + tx] = __float2half(t[tx][ty]);
}

// No-op spacer (capture slot = my launch index 3 -> qkv_gemm).
__global__ void spacer_kernel() {}

// ---------------------------------------------------------------------------
// Window-3 attention (fp16 qkv in, fp16 att out)
// ---------------------------------------------------------------------------
__global__ __launch_bounds__(256)
void attn_win3() {
    const int tid = threadIdx.x;
    const int m   = blockIdx.x * 2 + (tid >> 7);
    const int t   = tid & 127;
    const int h   = t >> 4;
    const int g   = t & 15;
    const int l   = m & (LL - 1);

    const size_t rowb = (size_t)m * NQKV;
    const int    co   = h * 64 + g * 4;

    const uint2 qraw = *reinterpret_cast<const uint2*>(g_qkv + rowb + co);
    const float2 qa = __half22float2(*reinterpret_cast<const __half2*>(&qraw.x));
    const float2 qb = __half22float2(*reinterpret_cast<const __half2*>(&qraw.y));

    float  s[3];
    float2 va[3], vb[3];
#pragma unroll
    for (int w = 0; w < 3; ++w) {
        const int lw = l + w - 1;
        float2 ka = make_float2(0.f, 0.f), kb = make_float2(0.f, 0.f);
        va[w] = make_float2(0.f, 0.f);
        vb[w] = make_float2(0.f, 0.f);
        if (lw >= 0 && lw < LL) {
            const size_t rb = rowb + (size_t)(w - 1) * NQKV;
            const uint2 kr = *reinterpret_cast<const uint2*>(g_qkv + rb + DD + co);
            const uint2 vr = *reinterpret_cast<const uint2*>(g_qkv + rb + 2 * DD + co);
            ka = __half22float2(*reinterpret_cast<const __half2*>(&kr.x));
            kb = __half22float2(*reinterpret_cast<const __half2*>(&kr.y));
            va[w] = __half22float2(*reinterpret_cast<const __half2*>(&vr.x));
            vb[w] = __half22float2(*reinterpret_cast<const __half2*>(&vr.y));
        }
        float p = qa.x * ka.x + qa.y * ka.y + qb.x * kb.x + qb.y * kb.y;
        p += __shfl_xor_sync(0xffffffffu, p, 8);
        p += __shfl_xor_sync(0xffffffffu, p, 4);
        p += __shfl_xor_sync(0xffffffffu, p, 2);
        p += __shfl_xor_sync(0xffffffffu, p, 1);
        s[w] = p * 0.125f;   // 1/sqrt(64)
    }

    const float mx = fmaxf(s[0], fmaxf(s[1], s[2]));
    const float e0 = expf(s[0] - mx), e1 = expf(s[1] - mx), e2 = expf(s[2] - mx);
    const float inv = 1.f / (e0 + e1 + e2);

    __half o[4];
    o[0] = __float2half((e0 * va[0].x + e1 * va[1].x + e2 * va[2].x) * inv);
    o[1] = __float2half((e0 * va[0].y + e1 * va[1].y + e2 * va[2].y) * inv);
    o[2] = __float2half((e0 * vb[0].x + e1 * vb[1].x + e2 * vb[2].x) * inv);
    o[3] = __float2half((e0 * vb[0].y + e1 * vb[1].y + e2 * vb[2].y) * inv);

    *reinterpret_cast<uint2*>(g_A2 + (size_t)m * K2 + co) = *reinterpret_cast<uint2*>(o);
}

// ---------------------------------------------------------------------------
extern "C" void kernel_launch(void* const* d_in, const int* in_sizes, int n_in,
                              void* d_out, int out_size)
{
    const float* x  = (const float*)d_in[0];
    const float* Wq = (const float*)d_in[1];
    const float* bq = (const float*)d_in[2];
    const float* Wk = (const float*)d_in[3];
    const float* bk = (const float*)d_in[4];
    const float* Wv = (const float*)d_in[5];
    const float* bv = (const float*)d_in[6];
    const float* Wo = (const float*)d_in[7];
    const float* bo = (const float*)d_in[8];
    float* out = (float*)d_out;

    cudaFuncSetAttribute(qkv_gemm, cudaFuncAttributeMaxDynamicSharedMemorySize, Q_SMEM);
    cudaFuncSetAttribute(wo_gemm,  cudaFuncAttributeMaxDynamicSharedMemorySize, W_SMEM);

    dim3 blk(32, 32);
    // idx:   0              1           2        3 (capture)   4       5
    conv_x_kernel<<<dim3(LL / 32, NHID / 32, BB), blk>>>(x);
    conv_w_all<<<1408, blk>>>(Wq, Wk, Wv, Wo);
    spacer_kernel<<<1, 32>>>();
    qkv_gemm<<<dim3(12, 32), 128, Q_SMEM>>>(bq, bk, bv);
    attn_win3<<<MM / 2, 256>>>();
    wo_gemm<<<dim3(16, 32), 256, W_SMEM>>>(bo, out);
}

// round 14
// speedup vs baseline: 1.1387x; 1.1387x over previous
#include <cuda_runtime.h>
#include <cuda_fp16.h>
#include <cstdint>
#include <math.h>

// ---------------------------------------------------------------------------
// Problem constants
// ---------------------------------------------------------------------------
#define BB     8
#define NHID   256
#define LL     2048
#define DD     512            // q/k/v channels
#define DOUT   2048
#define MM     (BB*LL)        // 16384
#define NQKV   1536           // q|k|v fused N
#define K1     256            // QKV GEMM K
#define K2     512            // WO GEMM K

// Common chunk geometry: 128 rows x 64 k x 2B, SWZ 128B rows
#define CHUNK  16384

// qkv (B-resident): B panel 4 chunks (64KB) + A ring 3 chunks (48KB) = 112KB
#define Q_AOFF (4*CHUNK)
#define Q_SMEM (Q_AOFF + 3*CHUNK)     // 114688 -> 2 CTAs/SM

// wo (R11 streaming config): 3 stages x (A16K + B16K) = 96KB
#define W_STAGE_A CHUNK
#define W_STAGE_SZ (2*CHUNK)          // 32 KB
#define W_STAGES 3
#define W_SMEM (W_STAGES*W_STAGE_SZ)  // 98304 -> 2 CTAs/SM

// ---------------------------------------------------------------------------
// Scratch (device globals — sanctioned no-alloc path)
// ---------------------------------------------------------------------------
__device__ __half g_A1[(size_t)MM * K1];     // x^T  [m][k] fp16
__device__ __half g_B1[(size_t)NQKV * K1];   // [Wq|Wk|Wv]^T [n][k] fp16
__device__ __half g_A2[(size_t)MM * K2];     // att  [m][k] fp16
__device__ __half g_B2[(size_t)DOUT * K2];   // Wo^T [n][k] fp16
__device__ __half g_qkv[(size_t)MM * NQKV];  // fp16 q|k|v (bias included)

// ---------------------------------------------------------------------------
// Helpers (base-target PTX: cp.async, ldmatrix, mma.sync)
// ---------------------------------------------------------------------------
__device__ __forceinline__ uint32_t smem_u32(const void* p) {
    uint32_t a;
    asm("{ .reg .u64 t; cvta.to.shared.u64 t, %1; cvt.u32.u64 %0, t; }"
        : "=r"(a) : "l"(p));
    return a;
}

#define SWZ(x) ((x) ^ ((((x) >> 7) & 7) << 4))   // Swizzle<3,4,3>, 128B rows

#define CPASYNC16(dst, src) \
    asm volatile("cp.async.cg.shared.global [%0], [%1], 16;" \
                 :: "r"(dst), "l"(src))
#define CPCOMMIT() asm volatile("cp.async.commit_group;" ::: "memory")
#define CPWAIT(n)  asm volatile("cp.async.wait_group %0;" :: "n"(n) : "memory")

__device__ __forceinline__ void ldsm4(uint32_t& r0, uint32_t& r1,
                                      uint32_t& r2, uint32_t& r3, uint32_t a) {
    asm volatile("ldmatrix.sync.aligned.m8n8.x4.shared.b16 {%0,%1,%2,%3}, [%4];"
                 : "=r"(r0), "=r"(r1), "=r"(r2), "=r"(r3) : "r"(a));
}

__device__ __forceinline__ void mma16816(float* d, const uint32_t* a,
                                         const uint32_t* b) {
    asm volatile(
        "mma.sync.aligned.m16n8k16.row.col.f32.f16.f16.f32 "
        "{%0,%1,%2,%3}, {%4,%5,%6,%7}, {%8,%9}, {%0,%1,%2,%3};"
        : "+f"(d[0]), "+f"(d[1]), "+f"(d[2]), "+f"(d[3])
        : "r"(a[0]), "r"(a[1]), "r"(a[2]), "r"(a[3]), "r"(b[0]), "r"(b[1]));
}

// ---------------------------------------------------------------------------
// QKV GEMM (B-resident v2): g_qkv[m][n] = fp16( A1[m].B1[n] + bias[n] )
// TH=256: 8 warps as 4(M)x2(N), warp tile 32x64 (R11 microkernel, regs<=128).
// B panel (4 chunks, 64KB) resident; A streamed via 3-deep 16KB ring.
// m-group = 2 tiles/CTA -> 8 chunks/CTA. grid (12, 64) = 768 CTAs, 2 CTAs/SM.
// ---------------------------------------------------------------------------
__device__ __forceinline__ float qkv_bias(int n, const float* __restrict__ bq,
                                          const float* __restrict__ bk,
                                          const float* __restrict__ bv) {
    if (n < DD)     return bq[n];
    if (n < 2 * DD) return bk[n - DD];
    return bv[n - 2 * DD];
}

__global__ __launch_bounds__(256, 2)
void qkv_gemm(const float* __restrict__ bq, const float* __restrict__ bk,
              const float* __restrict__ bv) {
    extern __shared__ __align__(1024) char smem[];
    const uint32_t sb = smem_u32(smem);
    const int tid = threadIdx.x, wid = tid >> 5, lane = tid & 31;
    const int n0  = blockIdx.x * 128;
    const int m0g = blockIdx.y * 256;          // 2 m-tiles of 128
    const int wm  = (wid & 3) * 32;
    const int wn  = (wid >> 2) * 64;

    // Prologue: whole B panel (4 chunks) bundled with A chunk0 in group0.
    {
        const __half* Bsrc = g_B1 + (size_t)n0 * K1;
#pragma unroll
        for (int i = 0; i < 16; ++i) {
            const int idx = tid + i * 256;          // 0..4095
            const int ch = idx >> 10, r = (idx >> 3) & 127, c = idx & 7;
            CPASYNC16(sb + ch * CHUNK + SWZ(r * 128 + c * 16),
                      Bsrc + (size_t)r * K1 + ch * 64 + c * 8);
        }
    }
    auto load_a = [&](int j, int buf) {            // chunk j = (mt=j>>2, kc=j&3)
        const __half* Asrc = g_A1 + (size_t)(m0g + (j >> 2) * 128) * K1 + (j & 3) * 64;
#pragma unroll
        for (int i = 0; i < 4; ++i) {
            const int idx = tid + i * 256;          // 0..1023
            const int r = idx >> 3, c = idx & 7;
            CPASYNC16(sb + Q_AOFF + buf * CHUNK + SWZ(r * 128 + c * 16),
                      Asrc + (size_t)r * K1 + c * 8);
        }
    };
    load_a(0, 0); CPCOMMIT();       // group0 = B panel + A0
    load_a(1, 1); CPCOMMIT();       // group1 = A1

    float acc[2][8][4];
#pragma unroll
    for (int i = 0; i < 2; ++i)
#pragma unroll
        for (int j = 0; j < 8; ++j)
#pragma unroll
            for (int r = 0; r < 4; ++r) acc[i][j][r] = 0.f;

    const int aRow = wm + (lane & 15);
    const int aCol = (lane >> 4) << 4;
    const int bRow = wn + ((lane >> 4) << 3) + (lane & 7);
    const int bCol = ((lane >> 3) & 1) << 4;

    for (int i = 0; i < 8; ++i) {
        CPWAIT(1);
        __syncthreads();
        const uint32_t as = sb + Q_AOFF + (i % 3) * CHUNK;
        const uint32_t bs = sb + (i & 3) * CHUNK;
#pragma unroll
        for (int ks = 0; ks < 4; ++ks) {
            uint32_t af[2][4], bf[4][4];
#pragma unroll
            for (int mi = 0; mi < 2; ++mi) {
                const uint32_t a = as + SWZ((aRow + mi * 16) * 128 + ks * 32 + aCol);
                ldsm4(af[mi][0], af[mi][1], af[mi][2], af[mi][3], a);
            }
#pragma unroll
            for (int ni = 0; ni < 4; ++ni) {
                const uint32_t a = bs + SWZ((bRow + ni * 16) * 128 + ks * 32 + bCol);
                ldsm4(bf[ni][0], bf[ni][1], bf[ni][2], bf[ni][3], a);
            }
#pragma unroll
            for (int mi = 0; mi < 2; ++mi)
#pragma unroll
                for (int ni = 0; ni < 4; ++ni) {
                    mma16816(acc[mi][ni * 2],     af[mi], &bf[ni][0]);
                    mma16816(acc[mi][ni * 2 + 1], af[mi], &bf[ni][2]);
                }
        }
        const int nx = i + 2;
        if (nx < 8) load_a(nx, nx % 3);
        CPCOMMIT();

        if ((i & 3) == 3) {
            // m-tile finished: epilogue from registers (overlaps ring loads)
            const int mt  = i >> 2;
            const int wmg = m0g + mt * 128 + wm;
            const int wng = n0 + wn;
#pragma unroll
            for (int mi = 0; mi < 2; ++mi) {
                const int r0 = wmg + mi * 16 + (lane >> 2);
#pragma unroll
                for (int ni = 0; ni < 8; ++ni) {
                    const int n = wng + ni * 8 + 2 * (lane & 3);
                    const float b0 = qkv_bias(n, bq, bk, bv);
                    const float b1 = qkv_bias(n + 1, bq, bk, bv);
                    const __half2 v0 = __floats2half2_rn(acc[mi][ni][0] + b0, acc[mi][ni][1] + b1);
                    const __half2 v1 = __floats2half2_rn(acc[mi][ni][2] + b0, acc[mi][ni][3] + b1);
                    *reinterpret_cast<__half2*>(&g_qkv[(size_t)r0 * NQKV + n])       = v0;
                    *reinterpret_cast<__half2*>(&g_qkv[(size_t)(r0 + 8) * NQKV + n]) = v1;
#pragma unroll
                    for (int r = 0; r < 4; ++r) acc[mi][ni][r] = 0.f;
                }
            }
        }
    }
}

// ---------------------------------------------------------------------------
// WO GEMM (exact R11 config): out[b][n][l] = A2[m].B2[n] + bo[n], m = b*LL+l.
// TH=256: 8 warps as 4(M)x2(N), warp tile 32x64, 3-stage stream, 2 CTAs/SM.
// ---------------------------------------------------------------------------
#define CSTR 132
__global__ __launch_bounds__(256, 2)
void wo_gemm(const float* __restrict__ bo, float* __restrict__ out) {
    extern __shared__ __align__(1024) char smem[];
    const uint32_t sb = smem_u32(smem);
    const int tid = threadIdx.x, wid = tid >> 5, lane = tid & 31;
    const int n0 = blockIdx.x * 128;
    const int m0 = blockIdx.y * 128;
    const int b  = m0 / LL;
    const int l0 = m0 % LL;
    const int wm = (wid & 3) * 32;
    const int wn = (wid >> 2) * 64;

    const __half* Ag = g_A2 + (size_t)m0 * K2;
    const __half* Bg = g_B2 + (size_t)n0 * K2;

    auto load_stage = [&](int kt, int s) {
        const uint32_t as = sb + s * W_STAGE_SZ;
        const uint32_t bs = as + W_STAGE_A;
        const __half* Asrc = Ag + kt * 64;
        const __half* Bsrc = Bg + kt * 64;
#pragma unroll
        for (int i = 0; i < 4; ++i) {
            const int idx = tid + i * 256;
            const int r = idx >> 3, c = idx & 7;
            CPASYNC16(as + SWZ(r * 128 + c * 16), Asrc + (size_t)r * K2 + c * 8);
        }
#pragma unroll
        for (int i = 0; i < 4; ++i) {
            const int idx = tid + i * 256;
            const int r = idx >> 3, c = idx & 7;
            CPASYNC16(bs + SWZ(r * 128 + c * 16), Bsrc + (size_t)r * K2 + c * 8);
        }
    };

    float acc[2][8][4];
#pragma unroll
    for (int i = 0; i < 2; ++i)
#pragma unroll
        for (int j = 0; j < 8; ++j)
#pragma unroll
            for (int r = 0; r < 4; ++r) acc[i][j][r] = 0.f;

    const int KT = K2 / 64;   // 8
    int fetch = 0;
    for (; fetch < W_STAGES - 1; ++fetch) { load_stage(fetch, fetch); CPCOMMIT(); }
    CPWAIT(W_STAGES - 2);
    __syncthreads();

    const int aRow = wm + (lane & 15);
    const int aCol = (lane >> 4) << 4;
    const int bRow = wn + ((lane >> 4) << 3) + (lane & 7);
    const int bCol = ((lane >> 3) & 1) << 4;

    for (int kt = 0; kt < KT; ++kt) {
        const uint32_t as = sb + (kt % W_STAGES) * W_STAGE_SZ;
        const uint32_t bs = as + W_STAGE_A;
#pragma unroll
        for (int ks = 0; ks < 4; ++ks) {
            uint32_t af[2][4], bf[4][4];
#pragma unroll
            for (int mi = 0; mi < 2; ++mi) {
                const uint32_t a = as + SWZ((aRow + mi * 16) * 128 + ks * 32 + aCol);
                ldsm4(af[mi][0], af[mi][1], af[mi][2], af[mi][3], a);
            }
#pragma unroll
            for (int ni = 0; ni < 4; ++ni) {
                const uint32_t a = bs + SWZ((bRow + ni * 16) * 128 + ks * 32 + bCol);
                ldsm4(bf[ni][0], bf[ni][1], bf[ni][2], bf[ni][3], a);
            }
#pragma unroll
            for (int mi = 0; mi < 2; ++mi)
#pragma unroll
                for (int ni = 0; ni < 4; ++ni) {
                    mma16816(acc[mi][ni * 2],     af[mi], &bf[ni][0]);
                    mma16816(acc[mi][ni * 2 + 1], af[mi], &bf[ni][2]);
                }
        }
        if (fetch < KT) { load_stage(fetch, fetch % W_STAGES); ++fetch; }
        CPCOMMIT();
        CPWAIT(W_STAGES - 2);
        __syncthreads();
    }

    // Transpose through smem: Cs[n][m], n=128 rows, stride 132 floats
    float* Cs = reinterpret_cast<float*>(smem);
    __syncthreads();
#pragma unroll
    for (int mi = 0; mi < 2; ++mi) {
        const int m = wm + mi * 16 + (lane >> 2);
#pragma unroll
        for (int ni = 0; ni < 8; ++ni) {
            const int n = wn + ni * 8 + 2 * (lane & 3);
            Cs[(size_t)n * CSTR + m]           = acc[mi][ni][0];
            Cs[(size_t)(n + 1) * CSTR + m]     = acc[mi][ni][1];
            Cs[(size_t)n * CSTR + m + 8]       = acc[mi][ni][2];
            Cs[(size_t)(n + 1) * CSTR + m + 8] = acc[mi][ni][3];
        }
    }
    __syncthreads();

    float* outb = out + (size_t)b * DOUT * LL;
    for (int i = tid; i < 128 * 32; i += 256) {
        const int n = i >> 5;          // 0..127
        const int c = (i & 31) * 4;    // 0..124
        const float bv = bo[n0 + n];
        float4 v;
        v.x = Cs[(size_t)n * CSTR + c + 0] + bv;
        v.y = Cs[(size_t)n * CSTR + c + 1] + bv;
        v.z = Cs[(size_t)n * CSTR + c + 2] + bv;
        v.w = Cs[(size_t)n * CSTR + c + 3] + bv;
        *reinterpret_cast<float4*>(outb + (size_t)(n0 + n) * LL + l0 + c) = v;
    }
}

// ---------------------------------------------------------------------------
// Conversions (fp32 -> fp16, with transposes)
// ---------------------------------------------------------------------------
__global__ __launch_bounds__(1024)
void conv_x_kernel(const float* __restrict__ x) {
    __shared__ float t[32][33];
    const int b  = blockIdx.z;
    const int c0 = blockIdx.y * 32, l0 = blockIdx.x * 32;
    const int tx = threadIdx.x, ty = threadIdx.y;
    t[ty][tx] = x[((size_t)(b * NHID + c0 + ty)) * LL + l0 + tx];
    __syncthreads();
    g_A1[(size_t)(b * LL + l0 + ty) * K1 + c0 + tx] = __float2half(t[tx][ty]);
}

__global__ __launch_bounds__(1024)
void conv_w_all(const float* __restrict__ Wq, const float* __restrict__ Wk,
                const float* __restrict__ Wv, const float* __restrict__ Wo) {
    __shared__ float t[32][33];
    const int bid = blockIdx.x;
    const float* W;
    __half* dst;
    int N, roff, dstride, lb, ntiles;
    if (bid < 384) {
        const int sel = bid >> 7;
        lb = bid & 127;
        W = (sel == 0) ? Wq : (sel == 1) ? Wk : Wv;
        dst = g_B1; N = DD; roff = sel * DD; dstride = K1; ntiles = DD / 32;
    } else {
        lb = bid - 384;
        W = Wo; dst = g_B2; N = DOUT; roff = 0; dstride = K2; ntiles = DOUT / 32;
    }
    const int n0 = (lb % ntiles) * 32;
    const int k0 = (lb / ntiles) * 32;
    const int tx = threadIdx.x, ty = threadIdx.y;
    t[ty][tx] = W[(size_t)(k0 + ty) * N + n0 + tx];
    __syncthreads();
    dst[(size_t)(roff + n0 + ty) * dstride + k0 + tx] = __float2half(t[tx][ty]);
}

// ---------------------------------------------------------------------------
// Window-3 attention (fp16 qkv in, fp16 att out)
// ---------------------------------------------------------------------------
__global__ __launch_bounds__(256)
void attn_win3() {
    const int tid = threadIdx.x;
    const int m   = blockIdx.x * 2 + (tid >> 7);
    const int t   = tid & 127;
    const int h   = t >> 4;
    const int g   = t & 15;
    const int l   = m & (LL - 1);

    const size_t rowb = (size_t)m * NQKV;
    const int    co   = h * 64 + g * 4;

    const uint2 qraw = *reinterpret_cast<const uint2*>(g_qkv + rowb + co);
    const float2 qa = __half22float2(*reinterpret_cast<const __half2*>(&qraw.x));
    const float2 qb = __half22float2(*reinterpret_cast<const __half2*>(&qraw.y));

    float  s[3];
    float2 va[3], vb[3];
#pragma unroll
    for (int w = 0; w < 3; ++w) {
        const int lw = l + w - 1;
        float2 ka = make_float2(0.f, 0.f), kb = make_float2(0.f, 0.f);
        va[w] = make_float2(0.f, 0.f);
        vb[w] = make_float2(0.f, 0.f);
        if (lw >= 0 && lw < LL) {
            const size_t rb = rowb + (size_t)(w - 1) * NQKV;
            const uint2 kr = *reinterpret_cast<const uint2*>(g_qkv + rb + DD + co);
            const uint2 vr = *reinterpret_cast<const uint2*>(g_qkv + rb + 2 * DD + co);
            ka = __half22float2(*reinterpret_cast<const __half2*>(&kr.x));
            kb = __half22float2(*reinterpret_cast<const __half2*>(&kr.y));
            va[w] = __half22float2(*reinterpret_cast<const __half2*>(&vr.x));
            vb[w] = __half22float2(*reinterpret_cast<const __half2*>(&vr.y));
        }
        float p = qa.x * ka.x + qa.y * ka.y + qb.x * kb.x + qb.y * kb.y;
        p += __shfl_xor_sync(0xffffffffu, p, 8);
        p += __shfl_xor_sync(0xffffffffu, p, 4);
        p += __shfl_xor_sync(0xffffffffu, p, 2);
        p += __shfl_xor_sync(0xffffffffu, p, 1);
        s[w] = p * 0.125f;   // 1/sqrt(64)
    }

    const float mx = fmaxf(s[0], fmaxf(s[1], s[2]));
    const float e0 = expf(s[0] - mx), e1 = expf(s[1] - mx), e2 = expf(s[2] - mx);
    const float inv = 1.f / (e0 + e1 + e2);

    __half o[4];
    o[0] = __float2half((e0 * va[0].x + e1 * va[1].x + e2 * va[2].x) * inv);
    o[1] = __float2half((e0 * va[0].y + e1 * va[1].y + e2 * va[2].y) * inv);
    o[2] = __float2half((e0 * vb[0].x + e1 * vb[1].x + e2 * vb[2].x) * inv);
    o[3] = __float2half((e0 * vb[0].y + e1 * vb[1].y + e2 * vb[2].y) * inv);

    *reinterpret_cast<uint2*>(g_A2 + (size_t)m * K2 + co) = *reinterpret_cast<uint2*>(o);
}

// ---------------------------------------------------------------------------
extern "C" void kernel_launch(void* const* d_in, const int* in_sizes, int n_in,
                              void* d_out, int out_size)
{
    const float* x  = (const float*)d_in[0];
    const float* Wq = (const float*)d_in[1];
    const float* bq = (const float*)d_in[2];
    const float* Wk = (const float*)d_in[3];
    const float* bk = (const float*)d_in[4];
    const float* Wv = (const float*)d_in[5];
    const float* bv = (const float*)d_in[6];
    const float* Wo = (const float*)d_in[7];
    const float* bo = (const float*)d_in[8];
    float* out = (float*)d_out;

    cudaFuncSetAttribute(qkv_gemm, cudaFuncAttributeMaxDynamicSharedMemorySize, Q_SMEM);
    cudaFuncSetAttribute(wo_gemm,  cudaFuncAttributeMaxDynamicSharedMemorySize, W_SMEM);

    dim3 blk(32, 32);
    conv_x_kernel<<<dim3(LL / 32, NHID / 32, BB), blk>>>(x);
    conv_w_all<<<1408, blk>>>(Wq, Wk, Wv, Wo);
    qkv_gemm<<<dim3(12, 64), 256, Q_SMEM>>>(bq, bk, bv);
    attn_win3<<<MM / 2, 256>>>();
    wo_gemm<<<dim3(16, 128), 256, W_SMEM>>>(bo, out);
}

// round 16
// speedup vs baseline: 1.1997x; 1.0536x over previous
#include <cuda_runtime.h>
#include <cuda_fp16.h>
#include <cstdint>
#include <math.h>

// ---------------------------------------------------------------------------
// Problem constants
// ---------------------------------------------------------------------------
#define BB     8
#define NHID   256
#define LL     2048
#define DD     512            // q/k/v channels
#define DOUT   2048
#define MM     (BB*LL)        // 16384
#define NQKV   1536           // q|k|v fused N
#define K1     256            // QKV GEMM K
#define K2     512            // WO GEMM K

// GEMM tiling (R11 proven): 256 threads = 8 warps as 4(M) x 2(N); warp 32x64.
// 96KB smem/CTA, 2 CTAs per SM.
#define BM     128
#define BN     128
#define BK     64
#define TH     256
#define STAGES 3
#define STAGE_A (BM*BK*2)          // 16 KB
#define STAGE_B (BN*BK*2)          // 16 KB
#define STAGE_SZ (STAGE_A+STAGE_B) // 32 KB
#define SMEM_SZ (STAGES*STAGE_SZ)  // 96 KB

// ---------------------------------------------------------------------------
// Scratch (device globals — sanctioned no-alloc path)
// ---------------------------------------------------------------------------
__device__ __half g_A1[(size_t)MM * K1];     // x^T  [m][k] fp16
__device__ __half g_B1[(size_t)NQKV * K1];   // [Wq|Wk|Wv]^T [n][k] fp16
__device__ __half g_A2[(size_t)MM * K2];     // att  [m][k] fp16
__device__ __half g_B2[(size_t)DOUT * K2];   // Wo^T [n][k] fp16
__device__ __half g_qkv[(size_t)MM * NQKV];  // fp16 q|k|v (bias included)

// ---------------------------------------------------------------------------
// Helpers (base-target PTX: cp.async, ldmatrix, mma.sync)
// ---------------------------------------------------------------------------
__device__ __forceinline__ uint32_t smem_u32(const void* p) {
    uint32_t a;
    asm("{ .reg .u64 t; cvta.to.shared.u64 t, %1; cvt.u32.u64 %0, t; }"
        : "=r"(a) : "l"(p));
    return a;
}

#define SWZ(x) ((x) ^ ((((x) >> 7) & 7) << 4))   // Swizzle<3,4,3>, 128B rows

#define CPASYNC16(dst, src) \
    asm volatile("cp.async.cg.shared.global [%0], [%1], 16;" \
                 :: "r"(dst), "l"(src))
#define CPCOMMIT() asm volatile("cp.async.commit_group;" ::: "memory")
#define CPWAIT(n)  asm volatile("cp.async.wait_group %0;" :: "n"(n) : "memory")

__device__ __forceinline__ void ldsm4(uint32_t& r0, uint32_t& r1,
                                      uint32_t& r2, uint32_t& r3, uint32_t a) {
    asm volatile("ldmatrix.sync.aligned.m8n8.x4.shared.b16 {%0,%1,%2,%3}, [%4];"
                 : "=r"(r0), "=r"(r1), "=r"(r2), "=r"(r3) : "r"(a));
}

__device__ __forceinline__ void mma16816(float* d, const uint32_t* a,
                                         const uint32_t* b) {
    asm volatile(
        "mma.sync.aligned.m16n8k16.row.col.f32.f16.f16.f32 "
        "{%0,%1,%2,%3}, {%4,%5,%6,%7}, {%8,%9}, {%0,%1,%2,%3};"
        : "+f"(d[0]), "+f"(d[1]), "+f"(d[2]), "+f"(d[3])
        : "r"(a[0]), "r"(a[1]), "r"(a[2]), "r"(a[3]), "r"(b[0]), "r"(b[1]));
}

// ---------------------------------------------------------------------------
// Shared mainloop (R11 structure + load-early prefetch).
// Per chunk: issue loads for s_{kt+2} -> compute s_kt -> wait -> sync.
// Consumption safety: compute s_kt relies on the PREVIOUS iteration's wait
// (wait(1) with a newer group pending, or wait(0) in the tail).
// ---------------------------------------------------------------------------
template <int KTOT>
__device__ __forceinline__ void gemm_mainloop(const __half* __restrict__ Ag,
                                              const __half* __restrict__ Bg,
                                              char* smem, float (&acc)[2][8][4])
{
    const int tid  = threadIdx.x;
    const int wid  = tid >> 5;
    const int lane = tid & 31;
    const int wm   = (wid & 3) * 32;
    const int wn   = (wid >> 2) * 64;
    const uint32_t sb = smem_u32(smem);
    const int KT = KTOT / BK;

    auto load_stage = [&](int kt, int s) {
        const uint32_t as = sb + s * STAGE_SZ;
        const uint32_t bs = as + STAGE_A;
        const __half* Asrc = Ag + kt * BK;
        const __half* Bsrc = Bg + kt * BK;
#pragma unroll
        for (int i = 0; i < 4; ++i) {           // A: 128 rows x 8 chunks = 1024
            const int idx = tid + i * TH;
            const int r = idx >> 3, c = idx & 7;
            CPASYNC16(as + SWZ(r * 128 + c * 16), Asrc + (size_t)r * KTOT + c * 8);
        }
#pragma unroll
        for (int i = 0; i < 4; ++i) {           // B: 128 rows x 8 chunks = 1024
            const int idx = tid + i * TH;
            const int r = idx >> 3, c = idx & 7;
            CPASYNC16(bs + SWZ(r * 128 + c * 16), Bsrc + (size_t)r * KTOT + c * 8);
        }
    };

    int fetch = 0;
    for (; fetch < STAGES - 1 && fetch < KT; ++fetch) { load_stage(fetch, fetch); CPCOMMIT(); }
    CPWAIT(STAGES - 2);
    __syncthreads();

    const int aRow = wm + (lane & 15);
    const int aCol = (lane >> 4) << 4;
    const int bRow = wn + ((lane >> 4) << 3) + (lane & 7);
    const int bCol = ((lane >> 3) & 1) << 4;

    for (int kt = 0; kt < KT; ++kt) {
        // 1. Issue next-stage loads FIRST (overwrite target last read at kt-1;
        //    all warps passed kt-1's trailing sync).
        const bool issued = (fetch < KT);
        if (issued) { load_stage(fetch, fetch % STAGES); ++fetch; CPCOMMIT(); }

        // 2. Compute current stage (ready per previous iteration's wait).
        const uint32_t as = sb + (kt % STAGES) * STAGE_SZ;
        const uint32_t bs = as + STAGE_A;
#pragma unroll
        for (int ks = 0; ks < 4; ++ks) {
            uint32_t af[2][4], bf[4][4];
#pragma unroll
            for (int mi = 0; mi < 2; ++mi) {
                const uint32_t a = as + SWZ((aRow + mi * 16) * 128 + ks * 32 + aCol);
                ldsm4(af[mi][0], af[mi][1], af[mi][2], af[mi][3], a);
            }
#pragma unroll
            for (int ni = 0; ni < 4; ++ni) {
                const uint32_t a = bs + SWZ((bRow + ni * 16) * 128 + ks * 32 + bCol);
                ldsm4(bf[ni][0], bf[ni][1], bf[ni][2], bf[ni][3], a);
            }
#pragma unroll
            for (int mi = 0; mi < 2; ++mi)
#pragma unroll
                for (int ni = 0; ni < 4; ++ni) {
                    mma16816(acc[mi][ni * 2],     af[mi], &bf[ni][0]);
                    mma16816(acc[mi][ni * 2 + 1], af[mi], &bf[ni][2]);
                }
        }

        // 3. Guarantee stage kt+1 for the next iteration.
        if (issued) { CPWAIT(STAGES - 2); } else { CPWAIT(0); }
        __syncthreads();
    }
}

// ---------------------------------------------------------------------------
// QKV GEMM: g_qkv[m][n] = fp16( A1[m] . B1[n] + bias[n] )
// ---------------------------------------------------------------------------
__device__ __forceinline__ float qkv_bias(int n, const float* __restrict__ bq,
                                          const float* __restrict__ bk,
                                          const float* __restrict__ bv) {
    if (n < DD)     return bq[n];
    if (n < 2 * DD) return bk[n - DD];
    return bv[n - 2 * DD];
}

__global__ __launch_bounds__(TH, 2)
void qkv_gemm(const float* __restrict__ bq, const float* __restrict__ bk,
              const float* __restrict__ bv) {
    extern __shared__ __align__(1024) char smem[];
    const int n0 = blockIdx.x * BN;
    const int m0 = blockIdx.y * BM;

    float acc[2][8][4];
#pragma unroll
    for (int i = 0; i < 2; ++i)
#pragma unroll
        for (int j = 0; j < 8; ++j)
#pragma unroll
            for (int r = 0; r < 4; ++r) acc[i][j][r] = 0.f;

    gemm_mainloop<K1>(g_A1 + (size_t)m0 * K1, g_B1 + (size_t)n0 * K1, smem, acc);

    const int wid = threadIdx.x >> 5, lane = threadIdx.x & 31;
    const int wm = m0 + (wid & 3) * 32;
    const int wn = n0 + (wid >> 2) * 64;
#pragma unroll
    for (int mi = 0; mi < 2; ++mi) {
        const int r0 = wm + mi * 16 + (lane >> 2);
#pragma unroll
        for (int ni = 0; ni < 8; ++ni) {
            const int n = wn + ni * 8 + 2 * (lane & 3);
            const float b0 = qkv_bias(n, bq, bk, bv);
            const float b1 = qkv_bias(n + 1, bq, bk, bv);
            const __half2 v0 = __floats2half2_rn(acc[mi][ni][0] + b0, acc[mi][ni][1] + b1);
            const __half2 v1 = __floats2half2_rn(acc[mi][ni][2] + b0, acc[mi][ni][3] + b1);
            *reinterpret_cast<__half2*>(&g_qkv[(size_t)r0 * NQKV + n])       = v0;
            *reinterpret_cast<__half2*>(&g_qkv[(size_t)(r0 + 8) * NQKV + n]) = v1;
        }
    }
}

// ---------------------------------------------------------------------------
// WO GEMM: out[b][n][l] = A2[m] . B2[n] + bo[n], m = b*LL + l (transposed store)
// ---------------------------------------------------------------------------
#define CSTR 132
__global__ __launch_bounds__(TH, 2)
void wo_gemm(const float* __restrict__ bo, float* __restrict__ out) {
    extern __shared__ __align__(1024) char smem[];
    const int n0 = blockIdx.x * BN;
    const int m0 = blockIdx.y * BM;
    const int b  = m0 / LL;
    const int l0 = m0 % LL;

    float acc[2][8][4];
#pragma unroll
    for (int i = 0; i < 2; ++i)
#pragma unroll
        for (int j = 0; j < 8; ++j)
#pragma unroll
            for (int r = 0; r < 4; ++r) acc[i][j][r] = 0.f;

    gemm_mainloop<K2>(g_A2 + (size_t)m0 * K2, g_B2 + (size_t)n0 * K2, smem, acc);

    // Transpose through smem: Cs[n][m], n=128 rows, stride 132 floats
    float* Cs = reinterpret_cast<float*>(smem);
    const int wid = threadIdx.x >> 5, lane = threadIdx.x & 31;
    const int wm = (wid & 3) * 32;
    const int wn = (wid >> 2) * 64;
    __syncthreads();
#pragma unroll
    for (int mi = 0; mi < 2; ++mi) {
        const int m = wm + mi * 16 + (lane >> 2);
#pragma unroll
        for (int ni = 0; ni < 8; ++ni) {
            const int n = wn + ni * 8 + 2 * (lane & 3);
            Cs[(size_t)n * CSTR + m]           = acc[mi][ni][0];
            Cs[(size_t)(n + 1) * CSTR + m]     = acc[mi][ni][1];
            Cs[(size_t)n * CSTR + m + 8]       = acc[mi][ni][2];
            Cs[(size_t)(n + 1) * CSTR + m + 8] = acc[mi][ni][3];
        }
    }
    __syncthreads();

    float* outb = out + (size_t)b * DOUT * LL;
    for (int i = threadIdx.x; i < BN * (BM / 4); i += TH) {
        const int n = i >> 5;          // 0..127
        const int c = (i & 31) * 4;    // 0..124
        const float bv = bo[n0 + n];
        float4 v;
        v.x = Cs[(size_t)n * CSTR + c + 0] + bv;
        v.y = Cs[(size_t)n * CSTR + c + 1] + bv;
        v.z = Cs[(size_t)n * CSTR + c + 2] + bv;
        v.w = Cs[(size_t)n * CSTR + c + 3] + bv;
        *reinterpret_cast<float4*>(outb + (size_t)(n0 + n) * LL + l0 + c) = v;
    }
}

// ---------------------------------------------------------------------------
// Conversions (fp32 -> fp16, with transposes)
// ---------------------------------------------------------------------------
__global__ __launch_bounds__(1024)
void conv_x_kernel(const float* __restrict__ x) {
    __shared__ float t[32][33];
    const int b  = blockIdx.z;
    const int c0 = blockIdx.y * 32, l0 = blockIdx.x * 32;
    const int tx = threadIdx.x, ty = threadIdx.y;
    t[ty][tx] = x[((size_t)(b * NHID + c0 + ty)) * LL + l0 + tx];
    __syncthreads();
    g_A1[(size_t)(b * LL + l0 + ty) * K1 + c0 + tx] = __float2half(t[tx][ty]);
}

__global__ __launch_bounds__(1024)
void conv_w_all(const float* __restrict__ Wq, const float* __restrict__ Wk,
                const float* __restrict__ Wv, const float* __restrict__ Wo) {
    __shared__ float t[32][33];
    const int bid = blockIdx.x;
    const float* W;
    __half* dst;
    int N, roff, dstride, lb, ntiles;
    if (bid < 384) {
        const int sel = bid >> 7;
        lb = bid & 127;
        W = (sel == 0) ? Wq : (sel == 1) ? Wk : Wv;
        dst = g_B1; N = DD; roff = sel * DD; dstride = K1; ntiles = DD / 32;
    } else {
        lb = bid - 384;
        W = Wo; dst = g_B2; N = DOUT; roff = 0; dstride = K2; ntiles = DOUT / 32;
    }
    const int n0 = (lb % ntiles) * 32;
    const int k0 = (lb / ntiles) * 32;
    const int tx = threadIdx.x, ty = threadIdx.y;
    t[ty][tx] = W[(size_t)(k0 + ty) * N + n0 + tx];
    __syncthreads();
    dst[(size_t)(roff + n0 + ty) * dstride + k0 + tx] = __float2half(t[tx][ty]);
}

// ---------------------------------------------------------------------------
// Window-3 attention, 8 dims/thread (uint4), 4 rows/block of 256 threads.
// ---------------------------------------------------------------------------
__global__ __launch_bounds__(256)
void attn_win3() {
    const int tid = threadIdx.x;
    const int m   = blockIdx.x * 4 + (tid >> 6);
    const int t   = tid & 63;        // 64 threads per row
    const int g   = t & 7;           // 8 threads per head, 8 dims each
    const int l   = m & (LL - 1);

    const size_t rowb = (size_t)m * NQKV;
    const int    co   = (t >> 3) * 64 + g * 8;

    const uint4 qr = *reinterpret_cast<const uint4*>(g_qkv + rowb + co);
    const __half2* qh = reinterpret_cast<const __half2*>(&qr);

    float  s[3];
    uint4  vr[3];
#pragma unroll
    for (int w = 0; w < 3; ++w) {
        const int lw = l + w - 1;
        float p = 0.f;
        vr[w] = make_uint4(0u, 0u, 0u, 0u);
        if (lw >= 0 && lw < LL) {
            const size_t rb = rowb + (size_t)(w - 1) * NQKV;
            const uint4 kr = *reinterpret_cast<const uint4*>(g_qkv + rb + DD + co);
            vr[w] = *reinterpret_cast<const uint4*>(g_qkv + rb + 2 * DD + co);
            const __half2* kh = reinterpret_cast<const __half2*>(&kr);
#pragma unroll
            for (int j = 0; j < 4; ++j) {
                const float2 qf = __half22float2(qh[j]);
                const float2 kf = __half22float2(kh[j]);
                p += qf.x * kf.x + qf.y * kf.y;
            }
        }
        p += __shfl_xor_sync(0xffffffffu, p, 4);
        p += __shfl_xor_sync(0xffffffffu, p, 2);
        p += __shfl_xor_sync(0xffffffffu, p, 1);
        s[w] = p * 0.125f;   // 1/sqrt(64)
    }

    const float mx = fmaxf(s[0], fmaxf(s[1], s[2]));
    const float e0 = expf(s[0] - mx), e1 = expf(s[1] - mx), e2 = expf(s[2] - mx);
    const float inv = 1.f / (e0 + e1 + e2);
    const float w0 = e0 * inv, w1 = e1 * inv, w2 = e2 * inv;

    uint4 o;
    __half2* oh = reinterpret_cast<__half2*>(&o);
    const __half2* v0 = reinterpret_cast<const __half2*>(&vr[0]);
    const __half2* v1 = reinterpret_cast<const __half2*>(&vr[1]);
    const __half2* v2 = reinterpret_cast<const __half2*>(&vr[2]);
#pragma unroll
    for (int j = 0; j < 4; ++j) {
        const float2 a = __half22float2(v0[j]);
        const float2 b = __half22float2(v1[j]);
        const float2 c = __half22float2(v2[j]);
        oh[j] = __floats2half2_rn(w0 * a.x + w1 * b.x + w2 * c.x,
                                  w0 * a.y + w1 * b.y + w2 * c.y);
    }
    *reinterpret_cast<uint4*>(g_A2 + (size_t)m * K2 + co) = o;
}

// ---------------------------------------------------------------------------
extern "C" void kernel_launch(void* const* d_in, const int* in_sizes, int n_in,
                              void* d_out, int out_size)
{
    const float* x  = (const float*)d_in[0];
    const float* Wq = (const float*)d_in[1];
    const float* bq = (const float*)d_in[2];
    const float* Wk = (const float*)d_in[3];
    const float* bk = (const float*)d_in[4];
    const float* Wv = (const float*)d_in[5];
    const float* bv = (const float*)d_in[6];
    const float* Wo = (const float*)d_in[7];
    const float* bo = (const float*)d_in[8];
    float* out = (float*)d_out;

    cudaFuncSetAttribute(qkv_gemm, cudaFuncAttributeMaxDynamicSharedMemorySize, SMEM_SZ);
    cudaFuncSetAttribute(wo_gemm,  cudaFuncAttributeMaxDynamicSharedMemorySize, SMEM_SZ);

    dim3 blk(32, 32);
    conv_x_kernel<<<dim3(LL / 32, NHID / 32, BB), blk>>>(x);
    conv_w_all<<<1408, blk>>>(Wq, Wk, Wv, Wo);
    qkv_gemm<<<dim3(NQKV / BN, MM / BM), TH, SMEM_SZ>>>(bq, bk, bv);
    attn_win3<<<MM / 4, 256>>>();
    wo_gemm<<<dim3(DOUT / BN, MM / BM), TH, SMEM_SZ>>>(bo, out);
}